// round 3
// baseline (speedup 1.0000x reference)
#include <cuda_runtime.h>
#include <cstdint>

// Quantized SiLU (per-row scales), S=8192 rows, H=4096 cols:
//   x_f   = x * scale_x[row]
//   y_q   = clip(rint(sigmoid(x_f) / scale_y[row]), -127, 127)
//   y_f   = y_q * scale_y[row]
//   out_q = clip(rint((x_f * y_f) / scale_out[row]), -127, 127)
//
// Harness dtypes: int8 is not a supported harness dtype, so x arrives
// promoted to a 4-byte type (int32 or float32) — detected at runtime on
// device. Output is the flattened tuple (out_q, scale_out) promoted to
// float32: [S*H out_q values][S scale_out values].

__device__ int g_x_is_int32;   // runtime dtype flag (1 = int32, 0 = float32)

// ---- dtype detection: int32 in [-127,127] has top-9 bits all-0/all-1;
//      float32 of a nonzero small int never does. ----
__global__ void detect_dtype_kernel(const uint32_t* __restrict__ x, int nwords) {
    __shared__ int s_count;
    if (threadIdx.x == 0) s_count = 0;
    __syncthreads();
    int i = threadIdx.x;
    int intlike = 0;
    if (i < nwords) {
        uint32_t w = x[i];
        uint32_t top9 = w >> 23;
        intlike = (top9 == 0u || top9 == 0x1FFu) ? 1 : 0;
    }
    // warp-reduce then shared accumulate
    for (int off = 16; off > 0; off >>= 1)
        intlike += __shfl_down_sync(0xFFFFFFFF, intlike, off);
    if ((threadIdx.x & 31) == 0) atomicAdd(&s_count, intlike);
    __syncthreads();
    if (threadIdx.x == 0) g_x_is_int32 = (s_count * 2 > nwords) ? 1 : 0;
}

__device__ __forceinline__ float silu_q_one(float xf, float scale_y,
                                            float inv_sy, float inv_so) {
    float sig = 1.0f / (1.0f + expf(-xf));           // sigmoid(x_f)
    float yq  = rintf(sig * inv_sy);                  // requant sigmoid
    yq = fminf(fmaxf(yq, -127.0f), 127.0f);
    float yf  = yq * scale_y;                         // dequant
    float oq  = rintf(xf * yf * inv_so);              // requant product
    return fminf(fmaxf(oq, -127.0f), 127.0f);
}

// ---- main kernel: one int4 load (4 elems) + one float4 store per thread ----
__global__ void __launch_bounds__(256) silu_quant_f32_kernel(
    const int4* __restrict__ x,           // 4 elements per vector
    const float* __restrict__ scale_x_v,
    const float* __restrict__ scale_y_v,
    const float* __restrict__ scale_out_v,
    float4* __restrict__ out,
    int vecs_per_row)                     // H / 4
{
    int row = blockIdx.x;
    float scale_x = __ldg(&scale_x_v[row]);
    float scale_y = __ldg(&scale_y_v[row]);
    float inv_sy  = 1.0f / scale_y;
    float inv_so  = 1.0f / __ldg(&scale_out_v[row]);
    int x_is_int  = g_x_is_int32;

    long base = (long)row * vecs_per_row;
    for (int t = threadIdx.x; t < vecs_per_row; t += blockDim.x) {
        int4 v = x[base + t];
        float f0, f1, f2, f3;
        if (x_is_int) {
            f0 = (float)v.x; f1 = (float)v.y; f2 = (float)v.z; f3 = (float)v.w;
        } else {
            f0 = __int_as_float(v.x); f1 = __int_as_float(v.y);
            f2 = __int_as_float(v.z); f3 = __int_as_float(v.w);
        }
        float4 r;
        r.x = silu_q_one(f0 * scale_x, scale_y, inv_sy, inv_so);
        r.y = silu_q_one(f1 * scale_x, scale_y, inv_sy, inv_so);
        r.z = silu_q_one(f2 * scale_x, scale_y, inv_sy, inv_so);
        r.w = silu_q_one(f3 * scale_x, scale_y, inv_sy, inv_so);
        out[base + t] = r;
    }
}

// ---- tail: scale_out passthrough + zero any trailing padding ----
__global__ void tail_kernel(const float* __restrict__ scale_o,
                            float* __restrict__ dst, int S, int pad) {
    int i = blockIdx.x * blockDim.x + threadIdx.x;
    if (i < S) dst[i] = scale_o[i];
    else if (i < S + pad) dst[i] = 0.0f;
}

extern "C" void kernel_launch(void* const* d_in, const int* in_sizes, int n_in,
                              void* d_out, int out_size) {
    const void* x         = d_in[0];
    const float* scale_x  = (const float*)d_in[1];
    const float* scale_y  = (const float*)d_in[2];
    const float* scale_o  = (const float*)d_in[3];

    int S = in_sizes[1];            // 8192 rows (scale_x element count)
    int H = in_sizes[0] / S;        // 4096 cols
    long total = (long)S * H;
    int vecs_per_row = H / 4;       // 1024

    detect_dtype_kernel<<<1, 1024>>>((const uint32_t*)x, 1024);

    float* out = (float*)d_out;
    silu_quant_f32_kernel<<<S, 256>>>(
        (const int4*)x, scale_x, scale_y, scale_o,
        (float4*)out, vecs_per_row);

    long extra = (long)out_size - total;   // expected: S (scale_out tail)
    if (extra > 0) {
        int S_copy = (int)(extra < S ? extra : S);
        int pad = (int)(extra - S_copy);
        tail_kernel<<<(int)((extra + 255) / 256), 256>>>(
            scale_o, out + total, S_copy, pad);
    }
}

// round 4
// speedup vs baseline: 1.2605x; 1.2605x over previous
#include <cuda_runtime.h>
#include <cstdint>

// Quantized SiLU (per-row scales), S=8192 rows, H=4096 cols.
//   x_f   = x * scale_x[row]
//   y_q   = clip(rint(sigmoid(x_f) / scale_y[row]), -127, 127)   (sigmoid>0 => only upper clip binds)
//   y_f   = y_q * scale_y[row]
//   out_q = clip(rint((x_f * y_f) / scale_out[row]), -127, 127)
//
// x arrives promoted to a 4-byte type (int32 or float32). Values are always
// in [-127,127], so dtype is decodable per element branch-free: the wrong
// interpretation is always huge (float bits as int -> |v| ~ 1e9) or
// denormal/NaN (int bits as float), never in range.
//
// Output buffer: float32 [S*H out_q values][S scale_out values].

__device__ __forceinline__ float decode_elem(int w) {
    float fi = (float)w;            // int32 interpretation
    float ff = __int_as_float(w);   // float32 interpretation
    // legitimate values are in [-127,127]; if int-interpretation is out of
    // range, the word must be float bits. (w==0 -> 0.0 either way.)
    return (fabsf(fi) > 127.5f) ? ff : fi;
}

__device__ __forceinline__ float silu_q(float f, float scale_x, float c_ex2,
                                        float scale_y, float inv_sy, float inv_so) {
    float xf  = f * scale_x;
    // sigmoid(xf) = 1 / (1 + exp2(-xf*log2e));  c_ex2 = -scale_x*log2(e)
    float e   = exp2f(f * c_ex2);
    float sig = __frcp_rn(1.0f + e);
    float yq  = fminf(rintf(sig * inv_sy), 127.0f);   // sigmoid>0: no lower clip
    float yf  = yq * scale_y;
    float oq  = rintf(xf * yf * inv_so);
    return fminf(fmaxf(oq, -127.0f), 127.0f);
}

// Fast path: vecs_per_row == 1024 (H=4096), one CTA per row, 256 threads,
// 4 independent int4 loads up-front (MLP=4), 4 float4 stores.
__global__ void __launch_bounds__(256) silu_quant_main_kernel(
    const int4* __restrict__ x,
    const float* __restrict__ scale_x_v,
    const float* __restrict__ scale_y_v,
    const float* __restrict__ scale_out_v,
    float4* __restrict__ out,
    float* __restrict__ tail_dst,   // out + S*H (or null)
    int write_tail)
{
    int row = blockIdx.x;
    float scale_x = __ldg(&scale_x_v[row]);
    float scale_y = __ldg(&scale_y_v[row]);
    float scale_o = __ldg(&scale_out_v[row]);
    float inv_sy  = 1.0f / scale_y;
    float inv_so  = 1.0f / scale_o;
    float c_ex2   = -scale_x * 1.44269504088896340736f;

    long base = (long)row * 1024 + threadIdx.x;
    int4 v0 = x[base];
    int4 v1 = x[base + 256];
    int4 v2 = x[base + 512];
    int4 v3 = x[base + 768];

    float4 r0, r1, r2, r3;
    r0.x = silu_q(decode_elem(v0.x), scale_x, c_ex2, scale_y, inv_sy, inv_so);
    r0.y = silu_q(decode_elem(v0.y), scale_x, c_ex2, scale_y, inv_sy, inv_so);
    r0.z = silu_q(decode_elem(v0.z), scale_x, c_ex2, scale_y, inv_sy, inv_so);
    r0.w = silu_q(decode_elem(v0.w), scale_x, c_ex2, scale_y, inv_sy, inv_so);
    r1.x = silu_q(decode_elem(v1.x), scale_x, c_ex2, scale_y, inv_sy, inv_so);
    r1.y = silu_q(decode_elem(v1.y), scale_x, c_ex2, scale_y, inv_sy, inv_so);
    r1.z = silu_q(decode_elem(v1.z), scale_x, c_ex2, scale_y, inv_sy, inv_so);
    r1.w = silu_q(decode_elem(v1.w), scale_x, c_ex2, scale_y, inv_sy, inv_so);
    r2.x = silu_q(decode_elem(v2.x), scale_x, c_ex2, scale_y, inv_sy, inv_so);
    r2.y = silu_q(decode_elem(v2.y), scale_x, c_ex2, scale_y, inv_sy, inv_so);
    r2.z = silu_q(decode_elem(v2.z), scale_x, c_ex2, scale_y, inv_sy, inv_so);
    r2.w = silu_q(decode_elem(v2.w), scale_x, c_ex2, scale_y, inv_sy, inv_so);
    r3.x = silu_q(decode_elem(v3.x), scale_x, c_ex2, scale_y, inv_sy, inv_so);
    r3.y = silu_q(decode_elem(v3.y), scale_x, c_ex2, scale_y, inv_sy, inv_so);
    r3.z = silu_q(decode_elem(v3.z), scale_x, c_ex2, scale_y, inv_sy, inv_so);
    r3.w = silu_q(decode_elem(v3.w), scale_x, c_ex2, scale_y, inv_sy, inv_so);

    out[base]       = r0;
    out[base + 256] = r1;
    out[base + 512] = r2;
    out[base + 768] = r3;

    if (write_tail && threadIdx.x == 0) tail_dst[row] = scale_o;
}

// Generic fallback for unexpected shapes.
__global__ void __launch_bounds__(256) silu_quant_generic_kernel(
    const int* __restrict__ x,
    const float* __restrict__ scale_x_v,
    const float* __restrict__ scale_y_v,
    const float* __restrict__ scale_out_v,
    float* __restrict__ out,
    int H, long total)
{
    long i = (long)blockIdx.x * blockDim.x + threadIdx.x;
    if (i >= total) return;
    int row = (int)(i / H);
    float scale_x = scale_x_v[row];
    float scale_y = scale_y_v[row];
    float inv_sy  = 1.0f / scale_y;
    float inv_so  = 1.0f / scale_out_v[row];
    float c_ex2   = -scale_x * 1.44269504088896340736f;
    out[i] = silu_q(decode_elem(x[i]), scale_x, c_ex2, scale_y, inv_sy, inv_so);
}

// Pad/tail for any leftover output elements beyond S*H (+S handled in main).
__global__ void tail_pad_kernel(const float* __restrict__ scale_o,
                                float* __restrict__ dst, int S, long extra) {
    long i = (long)blockIdx.x * blockDim.x + threadIdx.x;
    if (i >= extra) return;
    dst[i] = (i < S) ? scale_o[i] : 0.0f;
}

extern "C" void kernel_launch(void* const* d_in, const int* in_sizes, int n_in,
                              void* d_out, int out_size) {
    const void* x         = d_in[0];
    const float* scale_x  = (const float*)d_in[1];
    const float* scale_y  = (const float*)d_in[2];
    const float* scale_o  = (const float*)d_in[3];

    int S = in_sizes[1];            // rows (scale_x element count)
    int H = in_sizes[0] / S;        // cols
    long total = (long)S * H;
    long extra = (long)out_size - total;
    float* out = (float*)d_out;

    if (H == 4096) {
        int write_tail = (extra >= (long)S) ? 1 : 0;
        silu_quant_main_kernel<<<S, 256>>>(
            (const int4*)x, scale_x, scale_y, scale_o,
            (float4*)out, out + total, write_tail);
        if (extra > (long)S) {
            // zero any padding past the scale tail
            long pad = extra - S;
            tail_pad_kernel<<<(int)((pad + 255) / 256), 256>>>(
                scale_o + S, out + total + S, 0, pad);
        } else if (extra > 0 && !write_tail) {
            tail_pad_kernel<<<(int)((extra + 255) / 256), 256>>>(
                scale_o, out + total, (int)extra, extra);
        }
    } else {
        long blocks = (total + 255) / 256;
        silu_quant_generic_kernel<<<(unsigned)blocks, 256>>>(
            (const int*)x, scale_x, scale_y, scale_o, out, H, total);
        if (extra > 0) {
            tail_pad_kernel<<<(int)((extra + 255) / 256), 256>>>(
                scale_o, out + total, (int)(extra < S ? extra : S), extra);
        }
    }
}